// round 7
// baseline (speedup 1.0000x reference)
#include <cuda_runtime.h>
#include <cuda_bf16.h>
#include <math.h>
#include <stdint.h>

#define B_ 2
#define T_ 2048
#define D_ 2048
#define NH 16
#define KH 4
#define HD 128

// ============================================================================
// Scratch (static device globals — no allocation allowed)
// ============================================================================
__device__ float g_Q[(size_t)B_ * T_ * NH * HD];        // proj out (B,T,N,H) fp32
__device__ float g_KV[(size_t)B_ * T_ * 2 * KH * HD];   // proj out (B,T,[K|V]) fp32
__device__ float g_attn[(size_t)B_ * T_ * NH * HD];     // attn out fp32

// pre-split bf16x2 hi/lo words
__device__ uint32_t g_Xq_h[(size_t)B_ * T_ * D_ / 2],  g_Xq_l[(size_t)B_ * T_ * D_ / 2];
__device__ uint32_t g_Xkv_h[(size_t)B_ * T_ * D_ / 2], g_Xkv_l[(size_t)B_ * T_ * D_ / 2];
__device__ uint32_t g_Wq_h[(size_t)D_ / 2 * (NH * HD)], g_Wq_l[(size_t)D_ / 2 * (NH * HD)];
__device__ uint32_t g_Wkv_h[(size_t)D_ / 2 * (2 * KH * HD)], g_Wkv_l[(size_t)D_ / 2 * (2 * KH * HD)];
__device__ uint32_t g_Wo_h[(size_t)(NH * HD) / 2 * D_], g_Wo_l[(size_t)(NH * HD) / 2 * D_];
__device__ uint32_t g_Qh[(size_t)B_ * T_ * NH * 64],  g_Ql[(size_t)B_ * T_ * NH * 64];
__device__ uint32_t g_Kh[(size_t)B_ * T_ * KH * 64],  g_Kl[(size_t)B_ * T_ * KH * 64];
__device__ uint32_t g_Vh[(size_t)B_ * (T_/2) * KH * HD], g_Vl[(size_t)B_ * (T_/2) * KH * HD];
__device__ uint32_t g_At_h[(size_t)B_ * T_ * NH * 64], g_At_l[(size_t)B_ * T_ * NH * 64];

// ============================================================================
// Helpers
// ============================================================================
__device__ __forceinline__ void split_pair(float a, float b, uint32_t& hi, uint32_t& lo) {
    __nv_bfloat16 ha = __float2bfloat16_rn(a);
    __nv_bfloat16 hb = __float2bfloat16_rn(b);
    float ra = a - __bfloat162float(ha);
    float rb = b - __bfloat162float(hb);
    __nv_bfloat162 h2;
    h2.x = ha; h2.y = hb;
    __nv_bfloat162 l2 = __floats2bfloat162_rn(ra, rb);
    hi = *reinterpret_cast<uint32_t*>(&h2);
    lo = *reinterpret_cast<uint32_t*>(&l2);
}

__device__ __forceinline__ void mma_bf16(float* d, const uint32_t* a, const uint32_t* b) {
    asm volatile(
        "mma.sync.aligned.m16n8k16.row.col.f32.bf16.bf16.f32 "
        "{%0,%1,%2,%3}, {%4,%5,%6,%7}, {%8,%9}, {%0,%1,%2,%3};\n"
        : "+f"(d[0]), "+f"(d[1]), "+f"(d[2]), "+f"(d[3])
        : "r"(a[0]), "r"(a[1]), "r"(a[2]), "r"(a[3]), "r"(b[0]), "r"(b[1]));
}

__device__ __forceinline__ void cp16(uint32_t dst, const void* src) {
    asm volatile("cp.async.ca.shared.global [%0], [%1], 16;\n" ::"r"(dst), "l"(src));
}

// ============================================================================
// Split prepass kernels (memory-bound)
// ============================================================================
// Row-pair split: fp32 [R][C] -> hi/lo words [R][C/2], word = {x[2p], x[2p+1]}
__global__ void split_rowpair_kernel(const float* __restrict__ X,
                                     uint32_t* __restrict__ H, uint32_t* __restrict__ L,
                                     int total_words)
{
    int i = blockIdx.x * blockDim.x + threadIdx.x;
    if (i >= total_words) return;
    float2 v = *(const float2*)(X + 2 * (size_t)i);
    uint32_t h, l;
    split_pair(v.x, v.y, h, l);
    H[i] = h; L[i] = l;
}

// Col-pair split for weights: fp32 [Kd][N] -> words [Kd/2][ldw] at col offset co,
// word(kp,n) = {B[2kp][n], B[2kp+1][n]}
__global__ void split_colpair_kernel(const float* __restrict__ X,
                                     uint32_t* __restrict__ H, uint32_t* __restrict__ L,
                                     int N, int ldw, int co, int total)
{
    int i = blockIdx.x * blockDim.x + threadIdx.x;
    if (i >= total) return;
    int kp = i / N, n = i % N;
    float a = X[(size_t)(2 * kp) * N + n];
    float b = X[(size_t)(2 * kp + 1) * N + n];
    uint32_t h, l;
    split_pair(a, b, h, l);
    H[(size_t)kp * ldw + co + n] = h;
    L[(size_t)kp * ldw + co + n] = l;
}

// Fused RoPE + split: x fp32 rows of (heads*128) at stride ldx per bt;
// out H/L words (bt,heads,64). Thread per (bt, head, j<32).
__global__ void rope_split_kernel(const float* __restrict__ x, int ldx,
                                  const int* __restrict__ pos, int heads,
                                  uint32_t* __restrict__ H, uint32_t* __restrict__ L,
                                  int total)
{
    int idx = blockIdx.x * blockDim.x + threadIdx.x;
    if (idx >= total) return;
    int j = idx & 31;
    int rem = idx >> 5;
    int h = rem % heads;
    int bt = rem / heads;

    float p = (float)pos[bt];
    float s0, c0, s1, c1;
    float ts0 = powf(10000.f, (float)(4 * j) / 128.f);
    sincosf(p / ts0, &s0, &c0);
    float ts1 = powf(10000.f, (float)(4 * j + 2) / 128.f);
    sincosf(p / ts1, &s1, &c1);

    const float* base = x + (size_t)bt * ldx + h * HD;
    float a0 = base[2 * j],      a1 = base[2 * j + 1];
    float b0 = base[2 * j + 64], b1 = base[2 * j + 65];
    float o10 = a0 * c0 - b0 * s0, o11 = a1 * c1 - b1 * s1;
    float o20 = b0 * c0 + a0 * s0, o21 = b1 * c1 + a1 * s1;

    size_t ob = ((size_t)bt * heads + h) * 64;
    uint32_t hh, ll;
    split_pair(o10, o11, hh, ll); H[ob + j] = hh;      L[ob + j] = ll;
    split_pair(o20, o21, hh, ll); H[ob + 32 + j] = hh; L[ob + 32 + j] = ll;
}

// V split with t-pairing: KV fp32 (bt, 1024) cols [512,1024) hold V (k*128+h).
// out word i = ((b*(T/2)+tp)*KH + k)*128 + h = {V[2tp], V[2tp+1]}
__global__ void v_split_kernel(const float* __restrict__ KV,
                               uint32_t* __restrict__ H, uint32_t* __restrict__ L,
                               int total)
{
    int i = blockIdx.x * blockDim.x + threadIdx.x;
    if (i >= total) return;
    int h = i & 127;
    int rem = i >> 7;
    int k = rem & 3;
    rem >>= 2;
    int tp = rem % (T_ / 2);
    int b = rem / (T_ / 2);
    size_t r0 = ((size_t)(b * T_ + 2 * tp)) * 1024 + 512 + k * 128 + h;
    float a = KV[r0], bb = KV[r0 + 1024];
    uint32_t hh, ll;
    split_pair(a, bb, hh, ll);
    H[i] = hh; L[i] = ll;
}

// ============================================================================
// Pre-split bf16 3-product GEMM: C[M,N] = A * B (logical fp32 via hi/lo).
// A hi/lo: words [M][KP] (k-paired).  B hi/lo: words [KP][N] (k-paired rows).
// 128x128 tile, 16 kp (=32 k) per chunk, 256 threads, cp.async double buffer.
// ============================================================================
#define GA 20
#define GB 136
#define GEMM_SMEM_BYTES ((2 * 128 * GA * 2 + 2 * 16 * GB * 2) * 4)

__global__ void __launch_bounds__(256) bf16p_gemm_kernel(
    const uint32_t* __restrict__ Ah, const uint32_t* __restrict__ Al,
    const uint32_t* __restrict__ Bh, const uint32_t* __restrict__ Bl,
    float* __restrict__ C, int M, int N, int KP)
{
    extern __shared__ uint32_t gs[];
    uint32_t* AsH = gs;                      // [2][128*GA]
    uint32_t* AsL = AsH + 2 * 128 * GA;
    uint32_t* BsH = AsL + 2 * 128 * GA;      // [2][16*GB]
    uint32_t* BsL = BsH + 2 * 16 * GB;

    int bm = blockIdx.y * 128, bn = blockIdx.x * 128;
    int tid = threadIdx.x, warp = tid >> 5, lane = tid & 31;
    int wm = warp & 3, wn = warp >> 2;
    int m0 = wm * 32, n0 = wn * 64;
    int lr = lane >> 2, lc = lane & 3;

    uint32_t sAH = (uint32_t)__cvta_generic_to_shared(AsH);
    uint32_t sAL = (uint32_t)__cvta_generic_to_shared(AsL);
    uint32_t sBH = (uint32_t)__cvta_generic_to_shared(BsH);
    uint32_t sBL = (uint32_t)__cvta_generic_to_shared(BsL);

    float acc[2][8][4];
#pragma unroll
    for (int mt = 0; mt < 2; mt++)
#pragma unroll
        for (int nt = 0; nt < 8; nt++)
#pragma unroll
            for (int r = 0; r < 4; r++) acc[mt][nt][r] = 0.f;

    auto load_stage = [&](int stage, int kp0) {
        uint32_t aoff = (uint32_t)(stage * 128 * GA) * 4u;
        uint32_t boff = (uint32_t)(stage * 16 * GB) * 4u;
#pragma unroll
        for (int t = 0; t < 2; t++) {
            int c = tid + t * 256;
            int row = c >> 2, seg = (c & 3) << 2;   // 128 rows x 16 words
            size_t src = (size_t)(bm + row) * KP + kp0 + seg;
            uint32_t dst = (uint32_t)(row * GA + seg) * 4u;
            cp16(sAH + aoff + dst, Ah + src);
            cp16(sAL + aoff + dst, Al + src);
        }
#pragma unroll
        for (int t = 0; t < 2; t++) {
            int c = tid + t * 256;
            int kp = c >> 5, seg = (c & 31) << 2;   // 16 kp x 128 words
            size_t src = (size_t)(kp0 + kp) * N + bn + seg;
            uint32_t dst = (uint32_t)(kp * GB + seg) * 4u;
            cp16(sBH + boff + dst, Bh + src);
            cp16(sBL + boff + dst, Bl + src);
        }
        asm volatile("cp.async.commit_group;\n" ::);
    };

    int nK = KP >> 4;
    load_stage(0, 0);

    for (int kc = 0; kc < nK; kc++) {
        int stage = kc & 1;
        if (kc + 1 < nK) {
            load_stage(stage ^ 1, (kc + 1) << 4);
            asm volatile("cp.async.wait_group 1;\n" ::);
        } else {
            asm volatile("cp.async.wait_group 0;\n" ::);
        }
        __syncthreads();

        const uint32_t* aH = AsH + stage * 128 * GA;
        const uint32_t* aL = AsL + stage * 128 * GA;
        const uint32_t* bH = BsH + stage * 16 * GB;
        const uint32_t* bL = BsL + stage * 16 * GB;

#pragma unroll
        for (int ks = 0; ks < 2; ks++) {
            uint32_t fah[2][4], fal[2][4], fbh[8][2], fbl[8][2];
#pragma unroll
            for (int mt = 0; mt < 2; mt++) {
                int ra = (m0 + mt * 16 + lr) * GA + ks * 8 + lc;
                fah[mt][0] = aH[ra];     fah[mt][1] = aH[ra + 8 * GA];
                fah[mt][2] = aH[ra + 4]; fah[mt][3] = aH[ra + 8 * GA + 4];
                fal[mt][0] = aL[ra];     fal[mt][1] = aL[ra + 8 * GA];
                fal[mt][2] = aL[ra + 4]; fal[mt][3] = aL[ra + 8 * GA + 4];
            }
#pragma unroll
            for (int nt = 0; nt < 8; nt++) {
                int kb = (ks * 8 + lc) * GB + n0 + nt * 8 + lr;
                fbh[nt][0] = bH[kb]; fbh[nt][1] = bH[kb + 4 * GB];
                fbl[nt][0] = bL[kb]; fbl[nt][1] = bL[kb + 4 * GB];
            }
#pragma unroll
            for (int mt = 0; mt < 2; mt++)
#pragma unroll
                for (int nt = 0; nt < 8; nt++) {
                    mma_bf16(acc[mt][nt], fah[mt], fbh[nt]);  // hi*hi
                    mma_bf16(acc[mt][nt], fah[mt], fbl[nt]);  // hi*lo
                    mma_bf16(acc[mt][nt], fal[mt], fbh[nt]);  // lo*hi
                }
        }
        __syncthreads();
    }

#pragma unroll
    for (int mt = 0; mt < 2; mt++) {
        int row = bm + m0 + mt * 16 + lr;
#pragma unroll
        for (int nt = 0; nt < 8; nt++) {
            int col = bn + n0 + nt * 8 + (lc << 1);
            *(float2*)(C + (size_t)row * N + col) = make_float2(acc[mt][nt][0], acc[mt][nt][1]);
            *(float2*)(C + (size_t)(row + 8) * N + col) = make_float2(acc[mt][nt][2], acc[mt][nt][3]);
        }
    }
}

// ============================================================================
// Tensor-core causal flash attention — pre-split bf16 inputs.
// ============================================================================
#define QS_STRIDE 68
#define VS_STRIDE 132
#define SS_STRIDE 66
#define FLASH_SMEM_BYTES ((4 * 64 * QS_STRIDE + 2 * 32 * VS_STRIDE + 64 * SS_STRIDE + 192) * 4)

__global__ void __launch_bounds__(256) flash_kernel(
    const uint32_t* __restrict__ Qh, const uint32_t* __restrict__ Ql,
    const uint32_t* __restrict__ Kh, const uint32_t* __restrict__ Kl,
    const uint32_t* __restrict__ Vh, const uint32_t* __restrict__ Vl,
    float* __restrict__ Og)
{
    extern __shared__ uint32_t smw[];
    uint32_t* QsH = smw;
    uint32_t* QsL = QsH + 64 * QS_STRIDE;
    uint32_t* KsH = QsL + 64 * QS_STRIDE;
    uint32_t* KsL = KsH + 64 * QS_STRIDE;
    uint32_t* VsH = KsL + 64 * QS_STRIDE;
    uint32_t* VsL = VsH + 32 * VS_STRIDE;
    float* Ss   = (float*)(VsL + 32 * VS_STRIDE);
    float* mrow = Ss + 64 * SS_STRIDE;
    float* lrow = mrow + 64;
    float* arow = lrow + 64;

    int qt = blockIdx.x, n = blockIdx.y, b = blockIdx.z;
    int kvh = n >> 2;
    int tid = threadIdx.x, lane = tid & 31, warp = tid >> 5;
    int wq = warp & 3, wc = warp >> 2;
    int lr = lane >> 2, lc = lane & 3;
    const float scale = 0.08838834764831844f;  // 1/sqrt(128)

    int r0 = wq * 16;
    int n0 = wc * 32;
    int h0c = wc * 64;

    // Q tile (64 x 64 words)
    for (int i = tid; i < 64 * 16; i += 256) {
        int r = i >> 4, c4 = (i & 15) << 2;
        size_t g = (((size_t)(b * T_ + qt * 64 + r)) * NH + n) * 64 + c4;
        *(uint4*)&QsH[r * QS_STRIDE + c4] = *(const uint4*)(Qh + g);
        *(uint4*)&QsL[r * QS_STRIDE + c4] = *(const uint4*)(Ql + g);
    }
    if (tid < 64) { mrow[tid] = -1e30f; lrow[tid] = 0.f; }

    float o[8][4];
#pragma unroll
    for (int nt = 0; nt < 8; nt++)
#pragma unroll
        for (int r = 0; r < 4; r++) o[nt][r] = 0.f;

    int row = tid >> 2, part = tid & 3;

    for (int kt = 0; kt <= qt; ++kt) {
        __syncthreads();

        // K tile (64 x 64 words)
        for (int i = tid; i < 64 * 16; i += 256) {
            int r = i >> 4, c4 = (i & 15) << 2;
            size_t g = (((size_t)(b * T_ + kt * 64 + r)) * KH + kvh) * 64 + c4;
            *(uint4*)&KsH[r * QS_STRIDE + c4] = *(const uint4*)(Kh + g);
            *(uint4*)&KsL[r * QS_STRIDE + c4] = *(const uint4*)(Kl + g);
        }
        // V tile (32 tp x 128 words)
        for (int i = tid; i < 32 * 32; i += 256) {
            int kp = i >> 5, h4 = (i & 31) << 2;
            size_t g = (((size_t)(b * (T_ / 2) + kt * 32 + kp)) * KH + kvh) * HD + h4;
            *(uint4*)&VsH[kp * VS_STRIDE + h4] = *(const uint4*)(Vh + g);
            *(uint4*)&VsL[kp * VS_STRIDE + h4] = *(const uint4*)(Vl + g);
        }
        __syncthreads();

        // S = Q K^T
        float s[4][4];
#pragma unroll
        for (int nt = 0; nt < 4; nt++)
#pragma unroll
            for (int r = 0; r < 4; r++) s[nt][r] = 0.f;

#pragma unroll
        for (int kc = 0; kc < 8; kc++) {
            int pa = 8 * kc + lc;
            int ra = (r0 + lr) * QS_STRIDE, rb = (r0 + 8 + lr) * QS_STRIDE;
            uint32_t aH[4], aL[4];
            aH[0] = QsH[ra + pa];     aH[1] = QsH[rb + pa];
            aH[2] = QsH[ra + pa + 4]; aH[3] = QsH[rb + pa + 4];
            aL[0] = QsL[ra + pa];     aL[1] = QsL[rb + pa];
            aL[2] = QsL[ra + pa + 4]; aL[3] = QsL[rb + pa + 4];
#pragma unroll
            for (int nt = 0; nt < 4; nt++) {
                int nn = (n0 + nt * 8 + lr) * QS_STRIDE;
                uint32_t bH[2] = {KsH[nn + pa], KsH[nn + pa + 4]};
                uint32_t bL[2] = {KsL[nn + pa], KsL[nn + pa + 4]};
                mma_bf16(s[nt], aH, bH);
                mma_bf16(s[nt], aH, bL);
                mma_bf16(s[nt], aL, bH);
            }
        }

        bool diag = (kt == qt);
        int rq0 = r0 + lr, rq1 = r0 + 8 + lr;
#pragma unroll
        for (int nt = 0; nt < 4; nt++) {
            int col = n0 + nt * 8 + (lc << 1);
            float v0 = s[nt][0] * scale, v1 = s[nt][1] * scale;
            float v2 = s[nt][2] * scale, v3 = s[nt][3] * scale;
            if (diag) {
                if (col     > rq0) v0 = -1e30f;
                if (col + 1 > rq0) v1 = -1e30f;
                if (col     > rq1) v2 = -1e30f;
                if (col + 1 > rq1) v3 = -1e30f;
            }
            Ss[rq0 * SS_STRIDE + col]     = v0;
            Ss[rq0 * SS_STRIDE + col + 1] = v1;
            Ss[rq1 * SS_STRIDE + col]     = v2;
            Ss[rq1 * SS_STRIDE + col + 1] = v3;
        }
        __syncthreads();

        // Online softmax (4 threads per row)
        float mx = -1e30f;
#pragma unroll
        for (int c = 0; c < 16; ++c)
            mx = fmaxf(mx, Ss[row * SS_STRIDE + part * 16 + c]);
        mx = fmaxf(mx, __shfl_xor_sync(0xffffffffu, mx, 1));
        mx = fmaxf(mx, __shfl_xor_sync(0xffffffffu, mx, 2));
        float m_old = mrow[row];
        float m_new = fmaxf(m_old, mx);
        float sum = 0.f;
#pragma unroll
        for (int c = 0; c < 16; ++c) {
            float p = __expf(Ss[row * SS_STRIDE + part * 16 + c] - m_new);
            Ss[row * SS_STRIDE + part * 16 + c] = p;
            sum += p;
        }
        sum += __shfl_xor_sync(0xffffffffu, sum, 1);
        sum += __shfl_xor_sync(0xffffffffu, sum, 2);
        if (part == 0) {
            float alpha = __expf(m_old - m_new);
            arow[row] = alpha;
            mrow[row] = m_new;
            lrow[row] = lrow[row] * alpha + sum;
        }
        __syncthreads();

        // Rescale O, accumulate P @ V
        float al0 = arow[rq0], al1 = arow[rq1];
#pragma unroll
        for (int nt = 0; nt < 8; nt++) {
            o[nt][0] *= al0; o[nt][1] *= al0;
            o[nt][2] *= al1; o[nt][3] *= al1;
        }

#pragma unroll
        for (int kc = 0; kc < 4; kc++) {
            int ka = 16 * kc + (lc << 1);
            float2 p00 = *(float2*)&Ss[rq0 * SS_STRIDE + ka];
            float2 p01 = *(float2*)&Ss[rq0 * SS_STRIDE + ka + 8];
            float2 p10 = *(float2*)&Ss[rq1 * SS_STRIDE + ka];
            float2 p11 = *(float2*)&Ss[rq1 * SS_STRIDE + ka + 8];
            uint32_t aH[4], aL[4];
            split_pair(p00.x, p00.y, aH[0], aL[0]);
            split_pair(p10.x, p10.y, aH[1], aL[1]);
            split_pair(p01.x, p01.y, aH[2], aL[2]);
            split_pair(p11.x, p11.y, aH[3], aL[3]);
#pragma unroll
            for (int nt = 0; nt < 8; nt++) {
                int nn = h0c + nt * 8 + lr;
                int kpb = 8 * kc + lc;
                uint32_t bH[2] = {VsH[kpb * VS_STRIDE + nn], VsH[(kpb + 4) * VS_STRIDE + nn]};
                uint32_t bL[2] = {VsL[kpb * VS_STRIDE + nn], VsL[(kpb + 4) * VS_STRIDE + nn]};
                mma_bf16(o[nt], aH, bH);
                mma_bf16(o[nt], aH, bL);
                mma_bf16(o[nt], aL, bH);
            }
        }
    }

    int rq0 = r0 + lr, rq1 = r0 + 8 + lr;
    float li0 = 1.f / lrow[rq0], li1 = 1.f / lrow[rq1];
#pragma unroll
    for (int nt = 0; nt < 8; nt++) {
        int col = h0c + nt * 8 + (lc << 1);
        float* d0 = Og + (((size_t)(b * T_ + qt * 64 + rq0)) * NH + n) * HD + col;
        float* d1 = Og + (((size_t)(b * T_ + qt * 64 + rq1)) * NH + n) * HD + col;
        *(float2*)d0 = make_float2(o[nt][0] * li0, o[nt][1] * li0);
        *(float2*)d1 = make_float2(o[nt][2] * li1, o[nt][3] * li1);
    }
}

// ============================================================================
// Launch
// ============================================================================
extern "C" void kernel_launch(void* const* d_in, const int* in_sizes, int n_in,
                              void* d_out, int out_size)
{
    const float* Xq  = (const float*)d_in[0];
    const float* Xkv = (const float*)d_in[1];
    const int* qpos  = (const int*)d_in[2];
    const int* kvpos = (const int*)d_in[3];
    const float* Wq  = (const float*)d_in[4];
    const float* Wk  = (const float*)d_in[5];
    const float* Wv  = (const float*)d_in[6];
    const float* Wo  = (const float*)d_in[7];
    float* out = (float*)d_out;

    float *pQ, *pKV, *pA;
    uint32_t *pXqh, *pXql, *pXkvh, *pXkvl, *pWqh, *pWql, *pWkvh, *pWkvl, *pWoh, *pWol;
    uint32_t *pQh, *pQl, *pKh, *pKl, *pVh, *pVl, *pAth, *pAtl;
    cudaGetSymbolAddress((void**)&pQ, g_Q);
    cudaGetSymbolAddress((void**)&pKV, g_KV);
    cudaGetSymbolAddress((void**)&pA, g_attn);
    cudaGetSymbolAddress((void**)&pXqh, g_Xq_h);   cudaGetSymbolAddress((void**)&pXql, g_Xq_l);
    cudaGetSymbolAddress((void**)&pXkvh, g_Xkv_h); cudaGetSymbolAddress((void**)&pXkvl, g_Xkv_l);
    cudaGetSymbolAddress((void**)&pWqh, g_Wq_h);   cudaGetSymbolAddress((void**)&pWql, g_Wq_l);
    cudaGetSymbolAddress((void**)&pWkvh, g_Wkv_h); cudaGetSymbolAddress((void**)&pWkvl, g_Wkv_l);
    cudaGetSymbolAddress((void**)&pWoh, g_Wo_h);   cudaGetSymbolAddress((void**)&pWol, g_Wo_l);
    cudaGetSymbolAddress((void**)&pQh, g_Qh);      cudaGetSymbolAddress((void**)&pQl, g_Ql);
    cudaGetSymbolAddress((void**)&pKh, g_Kh);      cudaGetSymbolAddress((void**)&pKl, g_Kl);
    cudaGetSymbolAddress((void**)&pVh, g_Vh);      cudaGetSymbolAddress((void**)&pVl, g_Vl);
    cudaGetSymbolAddress((void**)&pAth, g_At_h);   cudaGetSymbolAddress((void**)&pAtl, g_At_l);

    cudaFuncSetAttribute(flash_kernel,
                         cudaFuncAttributeMaxDynamicSharedMemorySize, FLASH_SMEM_BYTES);
    cudaFuncSetAttribute(bf16p_gemm_kernel,
                         cudaFuncAttributeMaxDynamicSharedMemorySize, GEMM_SMEM_BYTES);

    int M = B_ * T_;  // 4096

    // --- Split prepass ---
    int wX = M * D_ / 2;  // 4,194,304
    split_rowpair_kernel<<<(wX + 255) / 256, 256>>>(Xq, pXqh, pXql, wX);
    split_rowpair_kernel<<<(wX + 255) / 256, 256>>>(Xkv, pXkvh, pXkvl, wX);
    int wWq = (D_ / 2) * (NH * HD);
    split_colpair_kernel<<<(wWq + 255) / 256, 256>>>(Wq, pWqh, pWql, NH * HD, NH * HD, 0, wWq);
    int wWk = (D_ / 2) * (KH * HD);
    split_colpair_kernel<<<(wWk + 255) / 256, 256>>>(Wk, pWkvh, pWkvl, KH * HD, 2 * KH * HD, 0, wWk);
    split_colpair_kernel<<<(wWk + 255) / 256, 256>>>(Wv, pWkvh, pWkvl, KH * HD, 2 * KH * HD, KH * HD, wWk);
    int wWo = ((NH * HD) / 2) * D_;
    split_colpair_kernel<<<(wWo + 255) / 256, 256>>>(Wo, pWoh, pWol, D_, D_, 0, wWo);

    // --- Projections (pre-split bf16 tensor-core GEMM) ---
    bf16p_gemm_kernel<<<dim3((NH * HD) / 128, M / 128), 256, GEMM_SMEM_BYTES>>>(
        pXqh, pXql, pWqh, pWql, pQ, M, NH * HD, D_ / 2);
    bf16p_gemm_kernel<<<dim3((2 * KH * HD) / 128, M / 128), 256, GEMM_SMEM_BYTES>>>(
        pXkvh, pXkvl, pWkvh, pWkvl, pKV, M, 2 * KH * HD, D_ / 2);

    // --- RoPE + split ---
    int totQ = M * NH * 32;
    rope_split_kernel<<<(totQ + 255) / 256, 256>>>(pQ, NH * HD, qpos, NH, pQh, pQl, totQ);
    int totK = M * KH * 32;
    rope_split_kernel<<<(totK + 255) / 256, 256>>>(pKV, 2 * KH * HD, kvpos, KH, pKh, pKl, totK);
    int totV = B_ * (T_ / 2) * KH * HD;
    v_split_kernel<<<(totV + 255) / 256, 256>>>(pKV, pVh, pVl, totV);

    // --- Flash attention ---
    flash_kernel<<<dim3(T_ / 64, NH, B_), 256, FLASH_SMEM_BYTES>>>(
        pQh, pQl, pKh, pKl, pVh, pVl, pA);

    // --- Split attn, O projection ---
    split_rowpair_kernel<<<(wX + 255) / 256, 256>>>(pA, pAth, pAtl, wX);
    bf16p_gemm_kernel<<<dim3(D_ / 128, M / 128), 256, GEMM_SMEM_BYTES>>>(
        pAth, pAtl, pWoh, pWol, out, M, D_, (NH * HD) / 2);
}

// round 9
// speedup vs baseline: 1.0339x; 1.0339x over previous
#include <cuda_runtime.h>
#include <cuda_bf16.h>
#include <math.h>
#include <stdint.h>

#define B_ 2
#define T_ 2048
#define D_ 2048
#define NH 16
#define KH 4
#define HD 128

// ============================================================================
// Scratch (static device globals — no allocation allowed)
// ============================================================================
__device__ float g_Q[(size_t)B_ * T_ * NH * HD];        // proj out (B,T,N,H) fp32
__device__ float g_KV[(size_t)B_ * T_ * 2 * KH * HD];   // proj out (B,T,[K|V]) fp32
__device__ float g_attn[(size_t)B_ * T_ * NH * HD];     // attn out fp32

// pre-split bf16x2 hi/lo words (k-paired layouts)
__device__ uint32_t g_Xq_h[(size_t)B_ * T_ * D_ / 2],  g_Xq_l[(size_t)B_ * T_ * D_ / 2];
__device__ uint32_t g_Xkv_h[(size_t)B_ * T_ * D_ / 2], g_Xkv_l[(size_t)B_ * T_ * D_ / 2];
__device__ uint32_t g_Wq_h[(size_t)D_ / 2 * (NH * HD)], g_Wq_l[(size_t)D_ / 2 * (NH * HD)];
__device__ uint32_t g_Wkv_h[(size_t)D_ / 2 * (2 * KH * HD)], g_Wkv_l[(size_t)D_ / 2 * (2 * KH * HD)];
__device__ uint32_t g_Wo_h[(size_t)(NH * HD) / 2 * D_], g_Wo_l[(size_t)(NH * HD) / 2 * D_];
__device__ uint32_t g_Qh[(size_t)B_ * T_ * NH * 64],  g_Ql[(size_t)B_ * T_ * NH * 64];
__device__ uint32_t g_Kh[(size_t)B_ * T_ * KH * 64],  g_Kl[(size_t)B_ * T_ * KH * 64];
__device__ uint32_t g_Vh[(size_t)B_ * (T_/2) * KH * HD], g_Vl[(size_t)B_ * (T_/2) * KH * HD];
__device__ uint32_t g_At_h[(size_t)B_ * T_ * NH * 64], g_At_l[(size_t)B_ * T_ * NH * 64];

// ============================================================================
// Helpers
// ============================================================================
__device__ __forceinline__ void split_pair(float a, float b, uint32_t& hi, uint32_t& lo) {
    __nv_bfloat16 ha = __float2bfloat16_rn(a);
    __nv_bfloat16 hb = __float2bfloat16_rn(b);
    float ra = a - __bfloat162float(ha);
    float rb = b - __bfloat162float(hb);
    __nv_bfloat162 h2;
    h2.x = ha; h2.y = hb;
    __nv_bfloat162 l2 = __floats2bfloat162_rn(ra, rb);
    hi = *reinterpret_cast<uint32_t*>(&h2);
    lo = *reinterpret_cast<uint32_t*>(&l2);
}

__device__ __forceinline__ void mma_bf16(float* d, const uint32_t* a, const uint32_t* b) {
    asm volatile(
        "mma.sync.aligned.m16n8k16.row.col.f32.bf16.bf16.f32 "
        "{%0,%1,%2,%3}, {%4,%5,%6,%7}, {%8,%9}, {%0,%1,%2,%3};\n"
        : "+f"(d[0]), "+f"(d[1]), "+f"(d[2]), "+f"(d[3])
        : "r"(a[0]), "r"(a[1]), "r"(a[2]), "r"(a[3]), "r"(b[0]), "r"(b[1]));
}

__device__ __forceinline__ void cp16(uint32_t dst, const void* src) {
    asm volatile("cp.async.ca.shared.global [%0], [%1], 16;\n" ::"r"(dst), "l"(src));
}

// ============================================================================
// Split prepass kernels (memory-bound) — unchanged from R7
// ============================================================================
__global__ void split_rowpair_kernel(const float* __restrict__ X,
                                     uint32_t* __restrict__ H, uint32_t* __restrict__ L,
                                     int total_words)
{
    int i = blockIdx.x * blockDim.x + threadIdx.x;
    if (i >= total_words) return;
    float2 v = *(const float2*)(X + 2 * (size_t)i);
    uint32_t h, l;
    split_pair(v.x, v.y, h, l);
    H[i] = h; L[i] = l;
}

__global__ void split_colpair_kernel(const float* __restrict__ X,
                                     uint32_t* __restrict__ H, uint32_t* __restrict__ L,
                                     int N, int ldw, int co, int total)
{
    int i = blockIdx.x * blockDim.x + threadIdx.x;
    if (i >= total) return;
    int kp = i / N, n = i % N;
    float a = X[(size_t)(2 * kp) * N + n];
    float b = X[(size_t)(2 * kp + 1) * N + n];
    uint32_t h, l;
    split_pair(a, b, h, l);
    H[(size_t)kp * ldw + co + n] = h;
    L[(size_t)kp * ldw + co + n] = l;
}

__global__ void rope_split_kernel(const float* __restrict__ x, int ldx,
                                  const int* __restrict__ pos, int heads,
                                  uint32_t* __restrict__ H, uint32_t* __restrict__ L,
                                  int total)
{
    int idx = blockIdx.x * blockDim.x + threadIdx.x;
    if (idx >= total) return;
    int j = idx & 31;
    int rem = idx >> 5;
    int h = rem % heads;
    int bt = rem / heads;

    float p = (float)pos[bt];
    float s0, c0, s1, c1;
    float ts0 = powf(10000.f, (float)(4 * j) / 128.f);
    sincosf(p / ts0, &s0, &c0);
    float ts1 = powf(10000.f, (float)(4 * j + 2) / 128.f);
    sincosf(p / ts1, &s1, &c1);

    const float* base = x + (size_t)bt * ldx + h * HD;
    float a0 = base[2 * j],      a1 = base[2 * j + 1];
    float b0 = base[2 * j + 64], b1 = base[2 * j + 65];
    float o10 = a0 * c0 - b0 * s0, o11 = a1 * c1 - b1 * s1;
    float o20 = b0 * c0 + a0 * s0, o21 = b1 * c1 + a1 * s1;

    size_t ob = ((size_t)bt * heads + h) * 64;
    uint32_t hh, ll;
    split_pair(o10, o11, hh, ll); H[ob + j] = hh;      L[ob + j] = ll;
    split_pair(o20, o21, hh, ll); H[ob + 32 + j] = hh; L[ob + 32 + j] = ll;
}

__global__ void v_split_kernel(const float* __restrict__ KV,
                               uint32_t* __restrict__ H, uint32_t* __restrict__ L,
                               int total)
{
    int i = blockIdx.x * blockDim.x + threadIdx.x;
    if (i >= total) return;
    int h = i & 127;
    int rem = i >> 7;
    int k = rem & 3;
    rem >>= 2;
    int tp = rem % (T_ / 2);
    int b = rem / (T_ / 2);
    size_t r0 = ((size_t)(b * T_ + 2 * tp)) * 1024 + 512 + k * 128 + h;
    float a = KV[r0], bb = KV[r0 + 1024];
    uint32_t hh, ll;
    split_pair(a, bb, hh, ll);
    H[i] = hh; L[i] = ll;
}

// ============================================================================
// Pre-split bf16 3-product GEMM, 256x128 CTA tile (warp tile 64x64).
// A hi/lo: words [M][KP] (k-paired).  B hi/lo: words [KP][N] (k-paired rows).
// 16 kp (=32 k) per chunk, 256 threads (8 warps 4x2), cp.async double buffer.
// Per-thread per-ks: 64 frag words feed 2048 logical MACs -> 8 MACs/smem-byte.
// ============================================================================
#define GA 20
#define GB 136
#define GEMM_SMEM_BYTES ((2 * 256 * GA * 2 + 2 * 16 * GB * 2) * 4)

__global__ void __launch_bounds__(256) bf16p_gemm_kernel(
    const uint32_t* __restrict__ Ah, const uint32_t* __restrict__ Al,
    const uint32_t* __restrict__ Bh, const uint32_t* __restrict__ Bl,
    float* __restrict__ C, int M, int N, int KP)
{
    extern __shared__ uint32_t gs[];
    uint32_t* AsH = gs;                      // [2][256*GA]
    uint32_t* AsL = AsH + 2 * 256 * GA;
    uint32_t* BsH = AsL + 2 * 256 * GA;      // [2][16*GB]
    uint32_t* BsL = BsH + 2 * 16 * GB;

    int bm = blockIdx.y * 256, bn = blockIdx.x * 128;
    int tid = threadIdx.x, warp = tid >> 5, lane = tid & 31;
    int wm = warp & 3, wn = warp >> 2;
    int m0 = wm * 64, n0 = wn * 64;
    int lr = lane >> 2, lc = lane & 3;

    uint32_t sAH = (uint32_t)__cvta_generic_to_shared(AsH);
    uint32_t sAL = (uint32_t)__cvta_generic_to_shared(AsL);
    uint32_t sBH = (uint32_t)__cvta_generic_to_shared(BsH);
    uint32_t sBL = (uint32_t)__cvta_generic_to_shared(BsL);

    float acc[4][8][4];
#pragma unroll
    for (int mt = 0; mt < 4; mt++)
#pragma unroll
        for (int nt = 0; nt < 8; nt++)
#pragma unroll
            for (int r = 0; r < 4; r++) acc[mt][nt][r] = 0.f;

    auto load_stage = [&](int stage, int kp0) {
        uint32_t aoff = (uint32_t)(stage * 256 * GA) * 4u;
        uint32_t boff = (uint32_t)(stage * 16 * GB) * 4u;
#pragma unroll
        for (int t = 0; t < 4; t++) {
            int c = tid + t * 256;
            int row = c >> 2, seg = (c & 3) << 2;   // 256 rows x 16 words
            size_t src = (size_t)(bm + row) * KP + kp0 + seg;
            uint32_t dst = (uint32_t)(row * GA + seg) * 4u;
            cp16(sAH + aoff + dst, Ah + src);
            cp16(sAL + aoff + dst, Al + src);
        }
#pragma unroll
        for (int t = 0; t < 2; t++) {
            int c = tid + t * 256;
            int kp = c >> 5, seg = (c & 31) << 2;   // 16 kp x 128 words
            size_t src = (size_t)(kp0 + kp) * N + bn + seg;
            uint32_t dst = (uint32_t)(kp * GB + seg) * 4u;
            cp16(sBH + boff + dst, Bh + src);
            cp16(sBL + boff + dst, Bl + src);
        }
        asm volatile("cp.async.commit_group;\n" ::);
    };

    int nK = KP >> 4;
    load_stage(0, 0);

    for (int kc = 0; kc < nK; kc++) {
        int stage = kc & 1;
        if (kc + 1 < nK) {
            load_stage(stage ^ 1, (kc + 1) << 4);
            asm volatile("cp.async.wait_group 1;\n" ::);
        } else {
            asm volatile("cp.async.wait_group 0;\n" ::);
        }
        __syncthreads();

        const uint32_t* aH = AsH + stage * 256 * GA;
        const uint32_t* aL = AsL + stage * 256 * GA;
        const uint32_t* bH = BsH + stage * 16 * GB;
        const uint32_t* bL = BsL + stage * 16 * GB;

#pragma unroll
        for (int ks = 0; ks < 2; ks++) {
            uint32_t fah[4][4], fal[4][4];
#pragma unroll
            for (int mt = 0; mt < 4; mt++) {
                int ra = (m0 + mt * 16 + lr) * GA + ks * 8 + lc;
                fah[mt][0] = aH[ra];     fah[mt][1] = aH[ra + 8 * GA];
                fah[mt][2] = aH[ra + 4]; fah[mt][3] = aH[ra + 8 * GA + 4];
                fal[mt][0] = aL[ra];     fal[mt][1] = aL[ra + 8 * GA];
                fal[mt][2] = aL[ra + 4]; fal[mt][3] = aL[ra + 8 * GA + 4];
            }
#pragma unroll
            for (int nt = 0; nt < 8; nt++) {
                int kb = (ks * 8 + lc) * GB + n0 + nt * 8 + lr;
                uint32_t fbh[2] = {bH[kb], bH[kb + 4 * GB]};
                uint32_t fbl[2] = {bL[kb], bL[kb + 4 * GB]};
#pragma unroll
                for (int mt = 0; mt < 4; mt++) {
                    mma_bf16(acc[mt][nt], fah[mt], fbh);  // hi*hi
                    mma_bf16(acc[mt][nt], fah[mt], fbl);  // hi*lo
                    mma_bf16(acc[mt][nt], fal[mt], fbh);  // lo*hi
                }
            }
        }
        __syncthreads();
    }

#pragma unroll
    for (int mt = 0; mt < 4; mt++) {
        int row = bm + m0 + mt * 16 + lr;
#pragma unroll
        for (int nt = 0; nt < 8; nt++) {
            int col = bn + n0 + nt * 8 + (lc << 1);
            *(float2*)(C + (size_t)row * N + col) = make_float2(acc[mt][nt][0], acc[mt][nt][1]);
            *(float2*)(C + (size_t)(row + 8) * N + col) = make_float2(acc[mt][nt][2], acc[mt][nt][3]);
        }
    }
}

// ============================================================================
// Tensor-core causal flash attention — pre-split bf16 inputs (R7, passing)
// ============================================================================
#define QS_STRIDE 68
#define VS_STRIDE 132
#define SS_STRIDE 66
#define FLASH_SMEM_BYTES ((4 * 64 * QS_STRIDE + 2 * 32 * VS_STRIDE + 64 * SS_STRIDE + 192) * 4)

__global__ void __launch_bounds__(256) flash_kernel(
    const uint32_t* __restrict__ Qh, const uint32_t* __restrict__ Ql,
    const uint32_t* __restrict__ Kh, const uint32_t* __restrict__ Kl,
    const uint32_t* __restrict__ Vh, const uint32_t* __restrict__ Vl,
    float* __restrict__ Og)
{
    extern __shared__ uint32_t smw[];
    uint32_t* QsH = smw;
    uint32_t* QsL = QsH + 64 * QS_STRIDE;
    uint32_t* KsH = QsL + 64 * QS_STRIDE;
    uint32_t* KsL = KsH + 64 * QS_STRIDE;
    uint32_t* VsH = KsL + 64 * QS_STRIDE;
    uint32_t* VsL = VsH + 32 * VS_STRIDE;
    float* Ss   = (float*)(VsL + 32 * VS_STRIDE);
    float* mrow = Ss + 64 * SS_STRIDE;
    float* lrow = mrow + 64;
    float* arow = lrow + 64;

    int qt = blockIdx.x, n = blockIdx.y, b = blockIdx.z;
    int kvh = n >> 2;
    int tid = threadIdx.x, lane = tid & 31, warp = tid >> 5;
    int wq = warp & 3, wc = warp >> 2;
    int lr = lane >> 2, lc = lane & 3;
    const float scale = 0.08838834764831844f;

    int r0 = wq * 16;
    int n0 = wc * 32;
    int h0c = wc * 64;

    for (int i = tid; i < 64 * 16; i += 256) {
        int r = i >> 4, c4 = (i & 15) << 2;
        size_t g = (((size_t)(b * T_ + qt * 64 + r)) * NH + n) * 64 + c4;
        *(uint4*)&QsH[r * QS_STRIDE + c4] = *(const uint4*)(Qh + g);
        *(uint4*)&QsL[r * QS_STRIDE + c4] = *(const uint4*)(Ql + g);
    }
    if (tid < 64) { mrow[tid] = -1e30f; lrow[tid] = 0.f; }

    float o[8][4];
#pragma unroll
    for (int nt = 0; nt < 8; nt++)
#pragma unroll
        for (int r = 0; r < 4; r++) o[nt][r] = 0.f;

    int row = tid >> 2, part = tid & 3;

    for (int kt = 0; kt <= qt; ++kt) {
        __syncthreads();

        for (int i = tid; i < 64 * 16; i += 256) {
            int r = i >> 4, c4 = (i & 15) << 2;
            size_t g = (((size_t)(b * T_ + kt * 64 + r)) * KH + kvh) * 64 + c4;
            *(uint4*)&KsH[r * QS_STRIDE + c4] = *(const uint4*)(Kh + g);
            *(uint4*)&KsL[r * QS_STRIDE + c4] = *(const uint4*)(Kl + g);
        }
        for (int i = tid; i < 32 * 32; i += 256) {
            int kp = i >> 5, h4 = (i & 31) << 2;
            size_t g = (((size_t)(b * (T_ / 2) + kt * 32 + kp)) * KH + kvh) * HD + h4;
            *(uint4*)&VsH[kp * VS_STRIDE + h4] = *(const uint4*)(Vh + g);
            *(uint4*)&VsL[kp * VS_STRIDE + h4] = *(const uint4*)(Vl + g);
        }
        __syncthreads();

        float s[4][4];
#pragma unroll
        for (int nt = 0; nt < 4; nt++)
#pragma unroll
            for (int r = 0; r < 4; r++) s[nt][r] = 0.f;

#pragma unroll
        for (int kc = 0; kc < 8; kc++) {
            int pa = 8 * kc + lc;
            int ra = (r0 + lr) * QS_STRIDE, rb = (r0 + 8 + lr) * QS_STRIDE;
            uint32_t aH[4], aL[4];
            aH[0] = QsH[ra + pa];     aH[1] = QsH[rb + pa];
            aH[2] = QsH[ra + pa + 4]; aH[3] = QsH[rb + pa + 4];
            aL[0] = QsL[ra + pa];     aL[1] = QsL[rb + pa];
            aL[2] = QsL[ra + pa + 4]; aL[3] = QsL[rb + pa + 4];
#pragma unroll
            for (int nt = 0; nt < 4; nt++) {
                int nn = (n0 + nt * 8 + lr) * QS_STRIDE;
                uint32_t bH[2] = {KsH[nn + pa], KsH[nn + pa + 4]};
                uint32_t bL[2] = {KsL[nn + pa], KsL[nn + pa + 4]};
                mma_bf16(s[nt], aH, bH);
                mma_bf16(s[nt], aH, bL);
                mma_bf16(s[nt], aL, bH);
            }
        }

        bool diag = (kt == qt);
        int rq0 = r0 + lr, rq1 = r0 + 8 + lr;
#pragma unroll
        for (int nt = 0; nt < 4; nt++) {
            int col = n0 + nt * 8 + (lc << 1);
            float v0 = s[nt][0] * scale, v1 = s[nt][1] * scale;
            float v2 = s[nt][2] * scale, v3 = s[nt][3] * scale;
            if (diag) {
                if (col     > rq0) v0 = -1e30f;
                if (col + 1 > rq0) v1 = -1e30f;
                if (col     > rq1) v2 = -1e30f;
                if (col + 1 > rq1) v3 = -1e30f;
            }
            Ss[rq0 * SS_STRIDE + col]     = v0;
            Ss[rq0 * SS_STRIDE + col + 1] = v1;
            Ss[rq1 * SS_STRIDE + col]     = v2;
            Ss[rq1 * SS_STRIDE + col + 1] = v3;
        }
        __syncthreads();

        float mx = -1e30f;
#pragma unroll
        for (int c = 0; c < 16; ++c)
            mx = fmaxf(mx, Ss[row * SS_STRIDE + part * 16 + c]);
        mx = fmaxf(mx, __shfl_xor_sync(0xffffffffu, mx, 1));
        mx = fmaxf(mx, __shfl_xor_sync(0xffffffffu, mx, 2));
        float m_old = mrow[row];
        float m_new = fmaxf(m_old, mx);
        float sum = 0.f;
#pragma unroll
        for (int c = 0; c < 16; ++c) {
            float p = __expf(Ss[row * SS_STRIDE + part * 16 + c] - m_new);
            Ss[row * SS_STRIDE + part * 16 + c] = p;
            sum += p;
        }
        sum += __shfl_xor_sync(0xffffffffu, sum, 1);
        sum += __shfl_xor_sync(0xffffffffu, sum, 2);
        if (part == 0) {
            float alpha = __expf(m_old - m_new);
            arow[row] = alpha;
            mrow[row] = m_new;
            lrow[row] = lrow[row] * alpha + sum;
        }
        __syncthreads();

        float al0 = arow[rq0], al1 = arow[rq1];
#pragma unroll
        for (int nt = 0; nt < 8; nt++) {
            o[nt][0] *= al0; o[nt][1] *= al0;
            o[nt][2] *= al1; o[nt][3] *= al1;
        }

#pragma unroll
        for (int kc = 0; kc < 4; kc++) {
            int ka = 16 * kc + (lc << 1);
            float2 p00 = *(float2*)&Ss[rq0 * SS_STRIDE + ka];
            float2 p01 = *(float2*)&Ss[rq0 * SS_STRIDE + ka + 8];
            float2 p10 = *(float2*)&Ss[rq1 * SS_STRIDE + ka];
            float2 p11 = *(float2*)&Ss[rq1 * SS_STRIDE + ka + 8];
            uint32_t aH[4], aL[4];
            split_pair(p00.x, p00.y, aH[0], aL[0]);
            split_pair(p10.x, p10.y, aH[1], aL[1]);
            split_pair(p01.x, p01.y, aH[2], aL[2]);
            split_pair(p11.x, p11.y, aH[3], aL[3]);
#pragma unroll
            for (int nt = 0; nt < 8; nt++) {
                int nn = h0c + nt * 8 + lr;
                int kpb = 8 * kc + lc;
                uint32_t bH[2] = {VsH[kpb * VS_STRIDE + nn], VsH[(kpb + 4) * VS_STRIDE + nn]};
                uint32_t bL[2] = {VsL[kpb * VS_STRIDE + nn], VsL[(kpb + 4) * VS_STRIDE + nn]};
                mma_bf16(o[nt], aH, bH);
                mma_bf16(o[nt], aH, bL);
                mma_bf16(o[nt], aL, bH);
            }
        }
    }

    int rq0 = r0 + lr, rq1 = r0 + 8 + lr;
    float li0 = 1.f / lrow[rq0], li1 = 1.f / lrow[rq1];
#pragma unroll
    for (int nt = 0; nt < 8; nt++) {
        int col = h0c + nt * 8 + (lc << 1);
        float* d0 = Og + (((size_t)(b * T_ + qt * 64 + rq0)) * NH + n) * HD + col;
        float* d1 = Og + (((size_t)(b * T_ + qt * 64 + rq1)) * NH + n) * HD + col;
        *(float2*)d0 = make_float2(o[nt][0] * li0, o[nt][1] * li0);
        *(float2*)d1 = make_float2(o[nt][2] * li1, o[nt][3] * li1);
    }
}

// ============================================================================
// Launch
// ============================================================================
extern "C" void kernel_launch(void* const* d_in, const int* in_sizes, int n_in,
                              void* d_out, int out_size)
{
    const float* Xq  = (const float*)d_in[0];
    const float* Xkv = (const float*)d_in[1];
    const int* qpos  = (const int*)d_in[2];
    const int* kvpos = (const int*)d_in[3];
    const float* Wq  = (const float*)d_in[4];
    const float* Wk  = (const float*)d_in[5];
    const float* Wv  = (const float*)d_in[6];
    const float* Wo  = (const float*)d_in[7];
    float* out = (float*)d_out;

    float *pQ, *pKV, *pA;
    uint32_t *pXqh, *pXql, *pXkvh, *pXkvl, *pWqh, *pWql, *pWkvh, *pWkvl, *pWoh, *pWol;
    uint32_t *pQh, *pQl, *pKh, *pKl, *pVh, *pVl, *pAth, *pAtl;
    cudaGetSymbolAddress((void**)&pQ, g_Q);
    cudaGetSymbolAddress((void**)&pKV, g_KV);
    cudaGetSymbolAddress((void**)&pA, g_attn);
    cudaGetSymbolAddress((void**)&pXqh, g_Xq_h);   cudaGetSymbolAddress((void**)&pXql, g_Xq_l);
    cudaGetSymbolAddress((void**)&pXkvh, g_Xkv_h); cudaGetSymbolAddress((void**)&pXkvl, g_Xkv_l);
    cudaGetSymbolAddress((void**)&pWqh, g_Wq_h);   cudaGetSymbolAddress((void**)&pWql, g_Wq_l);
    cudaGetSymbolAddress((void**)&pWkvh, g_Wkv_h); cudaGetSymbolAddress((void**)&pWkvl, g_Wkv_l);
    cudaGetSymbolAddress((void**)&pWoh, g_Wo_h);   cudaGetSymbolAddress((void**)&pWol, g_Wo_l);
    cudaGetSymbolAddress((void**)&pQh, g_Qh);      cudaGetSymbolAddress((void**)&pQl, g_Ql);
    cudaGetSymbolAddress((void**)&pKh, g_Kh);      cudaGetSymbolAddress((void**)&pKl, g_Kl);
    cudaGetSymbolAddress((void**)&pVh, g_Vh);      cudaGetSymbolAddress((void**)&pVl, g_Vl);
    cudaGetSymbolAddress((void**)&pAth, g_At_h);   cudaGetSymbolAddress((void**)&pAtl, g_At_l);

    cudaFuncSetAttribute(flash_kernel,
                         cudaFuncAttributeMaxDynamicSharedMemorySize, FLASH_SMEM_BYTES);
    cudaFuncSetAttribute(bf16p_gemm_kernel,
                         cudaFuncAttributeMaxDynamicSharedMemorySize, GEMM_SMEM_BYTES);

    int M = B_ * T_;  // 4096

    // --- Split prepass ---
    int wX = M * D_ / 2;
    split_rowpair_kernel<<<(wX + 255) / 256, 256>>>(Xq, pXqh, pXql, wX);
    split_rowpair_kernel<<<(wX + 255) / 256, 256>>>(Xkv, pXkvh, pXkvl, wX);
    int wWq = (D_ / 2) * (NH * HD);
    split_colpair_kernel<<<(wWq + 255) / 256, 256>>>(Wq, pWqh, pWql, NH * HD, NH * HD, 0, wWq);
    int wWk = (D_ / 2) * (KH * HD);
    split_colpair_kernel<<<(wWk + 255) / 256, 256>>>(Wk, pWkvh, pWkvl, KH * HD, 2 * KH * HD, 0, wWk);
    split_colpair_kernel<<<(wWk + 255) / 256, 256>>>(Wv, pWkvh, pWkvl, KH * HD, 2 * KH * HD, KH * HD, wWk);
    int wWo = ((NH * HD) / 2) * D_;
    split_colpair_kernel<<<(wWo + 255) / 256, 256>>>(Wo, pWoh, pWol, D_, D_, 0, wWo);

    // --- Projections (256x128-tile bf16 tensor-core GEMM) ---
    bf16p_gemm_kernel<<<dim3((NH * HD) / 128, M / 256), 256, GEMM_SMEM_BYTES>>>(
        pXqh, pXql, pWqh, pWql, pQ, M, NH * HD, D_ / 2);
    bf16p_gemm_kernel<<<dim3((2 * KH * HD) / 128, M / 256), 256, GEMM_SMEM_BYTES>>>(
        pXkvh, pXkvl, pWkvh, pWkvl, pKV, M, 2 * KH * HD, D_ / 2);

    // --- RoPE + split ---
    int totQ = M * NH * 32;
    rope_split_kernel<<<(totQ + 255) / 256, 256>>>(pQ, NH * HD, qpos, NH, pQh, pQl, totQ);
    int totK = M * KH * 32;
    rope_split_kernel<<<(totK + 255) / 256, 256>>>(pKV, 2 * KH * HD, kvpos, KH, pKh, pKl, totK);
    int totV = B_ * (T_ / 2) * KH * HD;
    v_split_kernel<<<(totV + 255) / 256, 256>>>(pKV, pVh, pVl, totV);

    // --- Flash attention ---
    flash_kernel<<<dim3(T_ / 64, NH, B_), 256, FLASH_SMEM_BYTES>>>(
        pQh, pQl, pKh, pKl, pVh, pVl, pA);

    // --- Split attn, O projection ---
    split_rowpair_kernel<<<(wX + 255) / 256, 256>>>(pA, pAth, pAtl, wX);
    bf16p_gemm_kernel<<<dim3(D_ / 128, M / 256), 256, GEMM_SMEM_BYTES>>>(
        pAth, pAtl, pWoh, pWol, out, M, D_, (NH * HD) / 2);
}

// round 11
// speedup vs baseline: 1.0417x; 1.0076x over previous
#include <cuda_runtime.h>
#include <cuda_bf16.h>
#include <math.h>
#include <stdint.h>

#define B_ 2
#define T_ 2048
#define D_ 2048
#define NH 16
#define KH 4
#define HD 128

// ============================================================================
// Scratch (static device globals — no allocation allowed)
// ============================================================================
__device__ uint32_t g_Xq_h[(size_t)B_ * T_ * D_ / 2],  g_Xq_l[(size_t)B_ * T_ * D_ / 2];
__device__ uint32_t g_Xkv_h[(size_t)B_ * T_ * D_ / 2], g_Xkv_l[(size_t)B_ * T_ * D_ / 2];
__device__ uint32_t g_Wq_h[(size_t)D_ / 2 * (NH * HD)], g_Wq_l[(size_t)D_ / 2 * (NH * HD)];
__device__ uint32_t g_Wkv_h[(size_t)D_ / 2 * (2 * KH * HD)], g_Wkv_l[(size_t)D_ / 2 * (2 * KH * HD)];
__device__ uint32_t g_Wo_h[(size_t)(NH * HD) / 2 * D_], g_Wo_l[(size_t)(NH * HD) / 2 * D_];
__device__ uint32_t g_Qh[(size_t)B_ * T_ * NH * 64],  g_Ql[(size_t)B_ * T_ * NH * 64];
__device__ uint32_t g_Kh[(size_t)B_ * T_ * KH * 64],  g_Kl[(size_t)B_ * T_ * KH * 64];
__device__ uint32_t g_Vh[(size_t)B_ * (T_/2) * KH * HD], g_Vl[(size_t)B_ * (T_/2) * KH * HD];
__device__ uint32_t g_At_h[(size_t)B_ * T_ * NH * 64], g_At_l[(size_t)B_ * T_ * NH * 64];

// ============================================================================
// Helpers
// ============================================================================
__device__ __forceinline__ void split_pair(float a, float b, uint32_t& hi, uint32_t& lo) {
    __nv_bfloat16 ha = __float2bfloat16_rn(a);
    __nv_bfloat16 hb = __float2bfloat16_rn(b);
    float ra = a - __bfloat162float(ha);
    float rb = b - __bfloat162float(hb);
    __nv_bfloat162 h2;
    h2.x = ha; h2.y = hb;
    __nv_bfloat162 l2 = __floats2bfloat162_rn(ra, rb);
    hi = *reinterpret_cast<uint32_t*>(&h2);
    lo = *reinterpret_cast<uint32_t*>(&l2);
}

__device__ __forceinline__ void mma_bf16(float* d, const uint32_t* a, const uint32_t* b) {
    asm volatile(
        "mma.sync.aligned.m16n8k16.row.col.f32.bf16.bf16.f32 "
        "{%0,%1,%2,%3}, {%4,%5,%6,%7}, {%8,%9}, {%0,%1,%2,%3};\n"
        : "+f"(d[0]), "+f"(d[1]), "+f"(d[2]), "+f"(d[3])
        : "r"(a[0]), "r"(a[1]), "r"(a[2]), "r"(a[3]), "r"(b[0]), "r"(b[1]));
}

__device__ __forceinline__ void cp16(uint32_t dst, const void* src) {
    asm volatile("cp.async.ca.shared.global [%0], [%1], 16;\n" ::"r"(dst), "l"(src));
}

// ============================================================================
// Split prepass kernels
// ============================================================================
__global__ void split_rowpair_kernel(const float* __restrict__ X,
                                     uint32_t* __restrict__ H, uint32_t* __restrict__ L,
                                     int total_words)
{
    int i = blockIdx.x * blockDim.x + threadIdx.x;
    if (i >= total_words) return;
    float2 v = *(const float2*)(X + 2 * (size_t)i);
    uint32_t h, l;
    split_pair(v.x, v.y, h, l);
    H[i] = h; L[i] = l;
}

__global__ void split_colpair_kernel(const float* __restrict__ X,
                                     uint32_t* __restrict__ H, uint32_t* __restrict__ L,
                                     int N, int ldw, int co, int total)
{
    int i = blockIdx.x * blockDim.x + threadIdx.x;
    if (i >= total) return;
    int kp = i / N, n = i % N;
    float a = X[(size_t)(2 * kp) * N + n];
    float b = X[(size_t)(2 * kp + 1) * N + n];
    uint32_t h, l;
    split_pair(a, b, h, l);
    H[(size_t)kp * ldw + co + n] = h;
    L[(size_t)kp * ldw + co + n] = l;
}

// ============================================================================
// Pre-split bf16 3-product GEMM, 256x128 CTA tile, fused format epilogues.
// mode 0: plain fp32 C write (O-proj)
// mode 1: RoPE + split -> OH/OL (Q-proj; heads = NH)
// mode 2: KV: head<KH -> RoPE+split K; head>=KH -> V t-pair split
// ============================================================================
#define GA 20
#define GB 136
#define STG_S 130
#define GEMM_MAIN_BYTES ((2 * 256 * GA * 2 + 2 * 16 * GB * 2) * 4)
#define GEMM_SMEM_BYTES (256 * STG_S * 4)

__global__ void __launch_bounds__(256) bf16p_gemm_kernel(
    const uint32_t* __restrict__ Ah, const uint32_t* __restrict__ Al,
    const uint32_t* __restrict__ Bh, const uint32_t* __restrict__ Bl,
    float* __restrict__ C,
    uint32_t* __restrict__ OH, uint32_t* __restrict__ OL,
    uint32_t* __restrict__ VH, uint32_t* __restrict__ VL,
    const int* __restrict__ pos,
    int M, int N, int KP, int mode)
{
    extern __shared__ uint32_t gs[];
    uint32_t* AsH = gs;
    uint32_t* AsL = AsH + 2 * 256 * GA;
    uint32_t* BsH = AsL + 2 * 256 * GA;
    uint32_t* BsL = BsH + 2 * 16 * GB;

    int bm = blockIdx.y * 256, bn = blockIdx.x * 128;
    int tid = threadIdx.x, warp = tid >> 5, lane = tid & 31;
    int wm = warp & 3, wn = warp >> 2;
    int m0 = wm * 64, n0 = wn * 64;
    int lr = lane >> 2, lc = lane & 3;

    uint32_t sAH = (uint32_t)__cvta_generic_to_shared(AsH);
    uint32_t sAL = (uint32_t)__cvta_generic_to_shared(AsL);
    uint32_t sBH = (uint32_t)__cvta_generic_to_shared(BsH);
    uint32_t sBL = (uint32_t)__cvta_generic_to_shared(BsL);

    float acc[4][8][4];
#pragma unroll
    for (int mt = 0; mt < 4; mt++)
#pragma unroll
        for (int nt = 0; nt < 8; nt++)
#pragma unroll
            for (int r = 0; r < 4; r++) acc[mt][nt][r] = 0.f;

    auto load_stage = [&](int stage, int kp0) {
        uint32_t aoff = (uint32_t)(stage * 256 * GA) * 4u;
        uint32_t boff = (uint32_t)(stage * 16 * GB) * 4u;
#pragma unroll
        for (int t = 0; t < 4; t++) {
            int c = tid + t * 256;
            int row = c >> 2, seg = (c & 3) << 2;
            size_t src = (size_t)(bm + row) * KP + kp0 + seg;
            uint32_t dst = (uint32_t)(row * GA + seg) * 4u;
            cp16(sAH + aoff + dst, Ah + src);
            cp16(sAL + aoff + dst, Al + src);
        }
#pragma unroll
        for (int t = 0; t < 2; t++) {
            int c = tid + t * 256;
            int kp = c >> 5, seg = (c & 31) << 2;
            size_t src = (size_t)(kp0 + kp) * N + bn + seg;
            uint32_t dst = (uint32_t)(kp * GB + seg) * 4u;
            cp16(sBH + boff + dst, Bh + src);
            cp16(sBL + boff + dst, Bl + src);
        }
        asm volatile("cp.async.commit_group;\n" ::);
    };

    int nK = KP >> 4;
    load_stage(0, 0);

    for (int kc = 0; kc < nK; kc++) {
        int stage = kc & 1;
        if (kc + 1 < nK) {
            load_stage(stage ^ 1, (kc + 1) << 4);
            asm volatile("cp.async.wait_group 1;\n" ::);
        } else {
            asm volatile("cp.async.wait_group 0;\n" ::);
        }
        __syncthreads();

        const uint32_t* aH = AsH + stage * 256 * GA;
        const uint32_t* aL = AsL + stage * 256 * GA;
        const uint32_t* bH = BsH + stage * 16 * GB;
        const uint32_t* bL = BsL + stage * 16 * GB;

#pragma unroll
        for (int ks = 0; ks < 2; ks++) {
            uint32_t fah[4][4], fal[4][4];
#pragma unroll
            for (int mt = 0; mt < 4; mt++) {
                int ra = (m0 + mt * 16 + lr) * GA + ks * 8 + lc;
                fah[mt][0] = aH[ra];     fah[mt][1] = aH[ra + 8 * GA];
                fah[mt][2] = aH[ra + 4]; fah[mt][3] = aH[ra + 8 * GA + 4];
                fal[mt][0] = aL[ra];     fal[mt][1] = aL[ra + 8 * GA];
                fal[mt][2] = aL[ra + 4]; fal[mt][3] = aL[ra + 8 * GA + 4];
            }
#pragma unroll
            for (int nt = 0; nt < 8; nt++) {
                int kb = (ks * 8 + lc) * GB + n0 + nt * 8 + lr;
                uint32_t fbh[2] = {bH[kb], bH[kb + 4 * GB]};
                uint32_t fbl[2] = {bL[kb], bL[kb + 4 * GB]};
#pragma unroll
                for (int mt = 0; mt < 4; mt++) {
                    mma_bf16(acc[mt][nt], fah[mt], fbh);
                    mma_bf16(acc[mt][nt], fah[mt], fbl);
                    mma_bf16(acc[mt][nt], fal[mt], fbh);
                }
            }
        }
        __syncthreads();
    }

    if (mode == 0) {
#pragma unroll
        for (int mt = 0; mt < 4; mt++) {
            int row = bm + m0 + mt * 16 + lr;
#pragma unroll
            for (int nt = 0; nt < 8; nt++) {
                int col = bn + n0 + nt * 8 + (lc << 1);
                *(float2*)(C + (size_t)row * N + col) = make_float2(acc[mt][nt][0], acc[mt][nt][1]);
                *(float2*)(C + (size_t)(row + 8) * N + col) = make_float2(acc[mt][nt][2], acc[mt][nt][3]);
            }
        }
        return;
    }

    // Stage fp32 tile (256 x 128) in smem, then convert in fused epilogue.
    float* stg = (float*)gs;
#pragma unroll
    for (int mt = 0; mt < 4; mt++) {
        int r = m0 + mt * 16 + lr;
#pragma unroll
        for (int nt = 0; nt < 8; nt++) {
            int cpair = n0 + nt * 8 + (lc << 1);
            *(float2*)&stg[r * STG_S + cpair] = make_float2(acc[mt][nt][0], acc[mt][nt][1]);
            *(float2*)&stg[(r + 8) * STG_S + cpair] = make_float2(acc[mt][nt][2], acc[mt][nt][3]);
        }
    }
    __syncthreads();

    int head = bn >> 7;
    if (mode == 1 || head < KH) {
        int heads = (mode == 1) ? NH : KH;
        for (int t = 0; t < 32; t++) {
            int i = tid + t * 256;
            int j = i & 31, r = i >> 5;
            int bt = bm + r;
            float p = (float)pos[bt];
            float s0, c0, s1, c1;
            float ts0 = powf(10000.f, (float)(4 * j) / 128.f);
            sincosf(p / ts0, &s0, &c0);
            float ts1 = powf(10000.f, (float)(4 * j + 2) / 128.f);
            sincosf(p / ts1, &s1, &c1);
            float a0 = stg[r * STG_S + 2 * j],      a1 = stg[r * STG_S + 2 * j + 1];
            float b0 = stg[r * STG_S + 2 * j + 64], b1 = stg[r * STG_S + 2 * j + 65];
            float o10 = a0 * c0 - b0 * s0, o11 = a1 * c1 - b1 * s1;
            float o20 = b0 * c0 + a0 * s0, o21 = b1 * c1 + a1 * s1;
            size_t ob = ((size_t)bt * heads + head) * 64;
            uint32_t hh, ll;
            split_pair(o10, o11, hh, ll); OH[ob + j] = hh;      OL[ob + j] = ll;
            split_pair(o20, o21, hh, ll); OH[ob + 32 + j] = hh; OL[ob + 32 + j] = ll;
        }
    } else {
        int k = head - KH;
        for (int t = 0; t < 64; t++) {
            int i = tid + t * 256;
            int h = i & 127, tp_l = i >> 7;
            int gt = bm + 2 * tp_l;
            int b = gt >> 11;
            int tp = (gt - b * T_) >> 1;
            float va = stg[(2 * tp_l) * STG_S + h];
            float vb = stg[(2 * tp_l + 1) * STG_S + h];
            uint32_t hh, ll;
            split_pair(va, vb, hh, ll);
            size_t oi = (((size_t)(b * (T_ / 2) + tp)) * KH + k) * 128 + h;
            VH[oi] = hh; VL[oi] = ll;
        }
    }
}

// ============================================================================
// Tensor-core causal flash attention — pre-split bf16 in, split bf16 out.
// ============================================================================
#define QS_STRIDE 68
#define VS_STRIDE 132
#define SS_STRIDE 66
#define FLASH_SMEM_BYTES ((4 * 64 * QS_STRIDE + 2 * 32 * VS_STRIDE + 64 * SS_STRIDE + 192) * 4)

__global__ void __launch_bounds__(256) flash_kernel(
    const uint32_t* __restrict__ Qh, const uint32_t* __restrict__ Ql,
    const uint32_t* __restrict__ Kh, const uint32_t* __restrict__ Kl,
    const uint32_t* __restrict__ Vh, const uint32_t* __restrict__ Vl,
    uint32_t* __restrict__ Ath, uint32_t* __restrict__ Atl)
{
    extern __shared__ uint32_t smw[];
    uint32_t* QsH = smw;
    uint32_t* QsL = QsH + 64 * QS_STRIDE;
    uint32_t* KsH = QsL + 64 * QS_STRIDE;
    uint32_t* KsL = KsH + 64 * QS_STRIDE;
    uint32_t* VsH = KsL + 64 * QS_STRIDE;
    uint32_t* VsL = VsH + 32 * VS_STRIDE;
    float* Ss   = (float*)(VsL + 32 * VS_STRIDE);
    float* mrow = Ss + 64 * SS_STRIDE;
    float* lrow = mrow + 64;
    float* arow = lrow + 64;

    int qt = blockIdx.x, n = blockIdx.y, b = blockIdx.z;
    int kvh = n >> 2;
    int tid = threadIdx.x, lane = tid & 31, warp = tid >> 5;
    int wq = warp & 3, wc = warp >> 2;
    int lr = lane >> 2, lc = lane & 3;
    const float scale = 0.08838834764831844f;

    int r0 = wq * 16;
    int n0 = wc * 32;
    int h0c = wc * 64;

    for (int i = tid; i < 64 * 16; i += 256) {
        int r = i >> 4, c4 = (i & 15) << 2;
        size_t g = (((size_t)(b * T_ + qt * 64 + r)) * NH + n) * 64 + c4;
        *(uint4*)&QsH[r * QS_STRIDE + c4] = *(const uint4*)(Qh + g);
        *(uint4*)&QsL[r * QS_STRIDE + c4] = *(const uint4*)(Ql + g);
    }
    if (tid < 64) { mrow[tid] = -1e30f; lrow[tid] = 0.f; }

    float o[8][4];
#pragma unroll
    for (int nt = 0; nt < 8; nt++)
#pragma unroll
        for (int r = 0; r < 4; r++) o[nt][r] = 0.f;

    int row = tid >> 2, part = tid & 3;

    for (int kt = 0; kt <= qt; ++kt) {
        __syncthreads();

        for (int i = tid; i < 64 * 16; i += 256) {
            int r = i >> 4, c4 = (i & 15) << 2;
            size_t g = (((size_t)(b * T_ + kt * 64 + r)) * KH + kvh) * 64 + c4;
            *(uint4*)&KsH[r * QS_STRIDE + c4] = *(const uint4*)(Kh + g);
            *(uint4*)&KsL[r * QS_STRIDE + c4] = *(const uint4*)(Kl + g);
        }
        for (int i = tid; i < 32 * 32; i += 256) {
            int kp = i >> 5, h4 = (i & 31) << 2;
            size_t g = (((size_t)(b * (T_ / 2) + kt * 32 + kp)) * KH + kvh) * HD + h4;
            *(uint4*)&VsH[kp * VS_STRIDE + h4] = *(const uint4*)(Vh + g);
            *(uint4*)&VsL[kp * VS_STRIDE + h4] = *(const uint4*)(Vl + g);
        }
        __syncthreads();

        float s[4][4];
#pragma unroll
        for (int nt = 0; nt < 4; nt++)
#pragma unroll
            for (int r = 0; r < 4; r++) s[nt][r] = 0.f;

#pragma unroll
        for (int kc = 0; kc < 8; kc++) {
            int pa = 8 * kc + lc;
            int ra = (r0 + lr) * QS_STRIDE, rb = (r0 + 8 + lr) * QS_STRIDE;
            uint32_t aH[4], aL[4];
            aH[0] = QsH[ra + pa];     aH[1] = QsH[rb + pa];
            aH[2] = QsH[ra + pa + 4]; aH[3] = QsH[rb + pa + 4];
            aL[0] = QsL[ra + pa];     aL[1] = QsL[rb + pa];
            aL[2] = QsL[ra + pa + 4]; aL[3] = QsL[rb + pa + 4];
#pragma unroll
            for (int nt = 0; nt < 4; nt++) {
                int nn = (n0 + nt * 8 + lr) * QS_STRIDE;
                uint32_t bH[2] = {KsH[nn + pa], KsH[nn + pa + 4]};
                uint32_t bL[2] = {KsL[nn + pa], KsL[nn + pa + 4]};
                mma_bf16(s[nt], aH, bH);
                mma_bf16(s[nt], aH, bL);
                mma_bf16(s[nt], aL, bH);
            }
        }

        bool diag = (kt == qt);
        int rq0 = r0 + lr, rq1 = r0 + 8 + lr;
#pragma unroll
        for (int nt = 0; nt < 4; nt++) {
            int col = n0 + nt * 8 + (lc << 1);
            float v0 = s[nt][0] * scale, v1 = s[nt][1] * scale;
            float v2 = s[nt][2] * scale, v3 = s[nt][3] * scale;
            if (diag) {
                if (col     > rq0) v0 = -1e30f;
                if (col + 1 > rq0) v1 = -1e30f;
                if (col     > rq1) v2 = -1e30f;
                if (col + 1 > rq1) v3 = -1e30f;
            }
            Ss[rq0 * SS_STRIDE + col]     = v0;
            Ss[rq0 * SS_STRIDE + col + 1] = v1;
            Ss[rq1 * SS_STRIDE + col]     = v2;
            Ss[rq1 * SS_STRIDE + col + 1] = v3;
        }
        __syncthreads();

        float mx = -1e30f;
#pragma unroll
        for (int c = 0; c < 16; ++c)
            mx = fmaxf(mx, Ss[row * SS_STRIDE + part * 16 + c]);
        mx = fmaxf(mx, __shfl_xor_sync(0xffffffffu, mx, 1));
        mx = fmaxf(mx, __shfl_xor_sync(0xffffffffu, mx, 2));
        float m_old = mrow[row];
        float m_new = fmaxf(m_old, mx);
        float sum = 0.f;
#pragma unroll
        for (int c = 0; c < 16; ++c) {
            float p = __expf(Ss[row * SS_STRIDE + part * 16 + c] - m_new);
            Ss[row * SS_STRIDE + part * 16 + c] = p;
            sum += p;
        }
        sum += __shfl_xor_sync(0xffffffffu, sum, 1);
        sum += __shfl_xor_sync(0xffffffffu, sum, 2);
        if (part == 0) {
            float alpha = __expf(m_old - m_new);
            arow[row] = alpha;
            mrow[row] = m_new;
            lrow[row] = lrow[row] * alpha + sum;
        }
        __syncthreads();

        float al0 = arow[rq0], al1 = arow[rq1];
#pragma unroll
        for (int nt = 0; nt < 8; nt++) {
            o[nt][0] *= al0; o[nt][1] *= al0;
            o[nt][2] *= al1; o[nt][3] *= al1;
        }

#pragma unroll
        for (int kc = 0; kc < 4; kc++) {
            int ka = 16 * kc + (lc << 1);
            float2 p00 = *(float2*)&Ss[rq0 * SS_STRIDE + ka];
            float2 p01 = *(float2*)&Ss[rq0 * SS_STRIDE + ka + 8];
            float2 p10 = *(float2*)&Ss[rq1 * SS_STRIDE + ka];
            float2 p11 = *(float2*)&Ss[rq1 * SS_STRIDE + ka + 8];
            uint32_t aH[4], aL[4];
            split_pair(p00.x, p00.y, aH[0], aL[0]);
            split_pair(p10.x, p10.y, aH[1], aL[1]);
            split_pair(p01.x, p01.y, aH[2], aL[2]);
            split_pair(p11.x, p11.y, aH[3], aL[3]);
#pragma unroll
            for (int nt = 0; nt < 8; nt++) {
                int nn = h0c + nt * 8 + lr;
                int kpb = 8 * kc + lc;
                uint32_t bH[2] = {VsH[kpb * VS_STRIDE + nn], VsH[(kpb + 4) * VS_STRIDE + nn]};
                uint32_t bL[2] = {VsL[kpb * VS_STRIDE + nn], VsL[(kpb + 4) * VS_STRIDE + nn]};
                mma_bf16(o[nt], aH, bH);
                mma_bf16(o[nt], aH, bL);
                mma_bf16(o[nt], aL, bH);
            }
        }
    }

    // Fused epilogue: normalize + split directly into O-proj input words.
    int rq0 = r0 + lr, rq1 = r0 + 8 + lr;
    float li0 = 1.f / lrow[rq0], li1 = 1.f / lrow[rq1];
    size_t base0 = ((size_t)(b * T_ + qt * 64 + rq0)) * (NH * 64) + n * 64;
    size_t base1 = ((size_t)(b * T_ + qt * 64 + rq1)) * (NH * 64) + n * 64;
#pragma unroll
    for (int nt = 0; nt < 8; nt++) {
        int colw = (h0c + nt * 8 + (lc << 1)) >> 1;
        uint32_t hh, ll;
        split_pair(o[nt][0] * li0, o[nt][1] * li0, hh, ll);
        Ath[base0 + colw] = hh; Atl[base0 + colw] = ll;
        split_pair(o[nt][2] * li1, o[nt][3] * li1, hh, ll);
        Ath[base1 + colw] = hh; Atl[base1 + colw] = ll;
    }
}

// ============================================================================
// Launch  (order chosen so ncu -s 5 -c 1 captures the Q-projection GEMM)
// ============================================================================
extern "C" void kernel_launch(void* const* d_in, const int* in_sizes, int n_in,
                              void* d_out, int out_size)
{
    const float* Xq  = (const float*)d_in[0];
    const float* Xkv = (const float*)d_in[1];
    const int* qpos  = (const int*)d_in[2];
    const int* kvpos = (const int*)d_in[3];
    const float* Wq  = (const float*)d_in[4];
    const float* Wk  = (const float*)d_in[5];
    const float* Wv  = (const float*)d_in[6];
    const float* Wo  = (const float*)d_in[7];
    float* out = (float*)d_out;

    uint32_t *pXqh, *pXql, *pXkvh, *pXkvl, *pWqh, *pWql, *pWkvh, *pWkvl, *pWoh, *pWol;
    uint32_t *pQh, *pQl, *pKh, *pKl, *pVh, *pVl, *pAth, *pAtl;
    cudaGetSymbolAddress((void**)&pXqh, g_Xq_h);   cudaGetSymbolAddress((void**)&pXql, g_Xq_l);
    cudaGetSymbolAddress((void**)&pXkvh, g_Xkv_h); cudaGetSymbolAddress((void**)&pXkvl, g_Xkv_l);
    cudaGetSymbolAddress((void**)&pWqh, g_Wq_h);   cudaGetSymbolAddress((void**)&pWql, g_Wq_l);
    cudaGetSymbolAddress((void**)&pWkvh, g_Wkv_h); cudaGetSymbolAddress((void**)&pWkvl, g_Wkv_l);
    cudaGetSymbolAddress((void**)&pWoh, g_Wo_h);   cudaGetSymbolAddress((void**)&pWol, g_Wo_l);
    cudaGetSymbolAddress((void**)&pQh, g_Qh);      cudaGetSymbolAddress((void**)&pQl, g_Ql);
    cudaGetSymbolAddress((void**)&pKh, g_Kh);      cudaGetSymbolAddress((void**)&pKl, g_Kl);
    cudaGetSymbolAddress((void**)&pVh, g_Vh);      cudaGetSymbolAddress((void**)&pVl, g_Vl);
    cudaGetSymbolAddress((void**)&pAth, g_At_h);   cudaGetSymbolAddress((void**)&pAtl, g_At_l);

    cudaFuncSetAttribute(flash_kernel,
                         cudaFuncAttributeMaxDynamicSharedMemorySize, FLASH_SMEM_BYTES);
    cudaFuncSetAttribute(bf16p_gemm_kernel,
                         cudaFuncAttributeMaxDynamicSharedMemorySize, GEMM_SMEM_BYTES);

    int M = B_ * T_;  // 4096

    // 1-4: weight splits
    int wWq = (D_ / 2) * (NH * HD);
    split_colpair_kernel<<<(wWq + 255) / 256, 256>>>(Wq, pWqh, pWql, NH * HD, NH * HD, 0, wWq);
    int wWk = (D_ / 2) * (KH * HD);
    split_colpair_kernel<<<(wWk + 255) / 256, 256>>>(Wk, pWkvh, pWkvl, KH * HD, 2 * KH * HD, 0, wWk);
    split_colpair_kernel<<<(wWk + 255) / 256, 256>>>(Wv, pWkvh, pWkvl, KH * HD, 2 * KH * HD, KH * HD, wWk);
    int wWo = ((NH * HD) / 2) * D_;
    split_colpair_kernel<<<(wWo + 255) / 256, 256>>>(Wo, pWoh, pWol, D_, D_, 0, wWo);

    // 5: Xq split
    int wX = M * D_ / 2;
    split_rowpair_kernel<<<(wX + 255) / 256, 256>>>(Xq, pXqh, pXql, wX);

    // 6: Q projection + fused RoPE/split  (ncu -s 5 -c 1 captures this launch)
    bf16p_gemm_kernel<<<dim3((NH * HD) / 128, M / 256), 256, GEMM_SMEM_BYTES>>>(
        pXqh, pXql, pWqh, pWql, nullptr, pQh, pQl, nullptr, nullptr, qpos,
        M, NH * HD, D_ / 2, 1);

    // 7: Xkv split
    split_rowpair_kernel<<<(wX + 255) / 256, 256>>>(Xkv, pXkvh, pXkvl, wX);

    // 8: KV projection + fused RoPE-K / V-pair split
    bf16p_gemm_kernel<<<dim3((2 * KH * HD) / 128, M / 256), 256, GEMM_SMEM_BYTES>>>(
        pXkvh, pXkvl, pWkvh, pWkvl, nullptr, pKh, pKl, pVh, pVl, kvpos,
        M, 2 * KH * HD, D_ / 2, 2);

    // 9: flash attention (fused split epilogue)
    flash_kernel<<<dim3(T_ / 64, NH, B_), 256, FLASH_SMEM_BYTES>>>(
        pQh, pQl, pKh, pKl, pVh, pVl, pAth, pAtl);

    // 10: O projection (plain fp32 out)
    bf16p_gemm_kernel<<<dim3(D_ / 128, M / 256), 256, GEMM_SMEM_BYTES>>>(
        pAth, pAtl, pWoh, pWol, out, nullptr, nullptr, nullptr, nullptr, nullptr,
        M, D_, (NH * HD) / 2, 0);
}